// round 17
// baseline (speedup 1.0000x reference)
#include <cuda_runtime.h>
#include <math.h>

// Problem constants (fixed by the reference)
#define POOL   100
#define NTASKS 10
#define NB_PT  (POOL / NTASKS)       // 10
#define PLEN   8
#define EMBD   768
#define BATCH  512
#define ED4    (EMBD / 4)            // 192

// sim: grid (16, POOL) x 1024 threads; one batch row per warp
#define SIM_G       16
#define SIM_THREADS 1024
#define SIM_ROWS    (BATCH / SIM_G)  // 32

// mega (round-15 proven config: 96.2 us, regs 40)
#define PMT_BLOCKS  BATCH            // 512
#define COPY_BLOCKS 2560

// Scratch (allocation-free per harness rules)
__device__ float g_sim[BATCH * POOL];

// ---------------------------------------------------------------------------
// Kernel A: fused diag + sim, with SPLIT phase-1 (two 4-deep load chains in
// parallel instead of one 8-deep chain) and no e_a staging (L2-hot reads).
// ---------------------------------------------------------------------------
__global__ void __launch_bounds__(SIM_THREADS) sim_fused_kernel(
        const float* __restrict__ x_querry,
        const float* __restrict__ e_a,
        const float* __restrict__ e_p,
        const int*   __restrict__ task_id_p) {
    const int task_end = (*task_id_p + 1) * NB_PT;
    const int k = blockIdx.y;
    if (k >= task_end) return;

    __shared__ float s_dA[EMBD];   // sum over l = 0..3
    __shared__ float s_dB[EMBD];   // sum over l = 4..7

    const int tid = threadIdx.x;
    const float* epk = e_p + (size_t)k * PLEN * EMBD;

    // Phase 1: 1024 threads cover 768*2 half-diag tasks (4-load chains).
    for (int t = tid; t < 2 * EMBD; t += SIM_THREADS) {
        int half = t >> 9;              // 0: l=0..3 -> but EMBD=768, use t<EMBD
        // map: t in [0,768) -> s_dA[t];  t in [768,1536) -> s_dB[t-768]
        int d = (t < EMBD) ? t : (t - EMBD);
        const float* p = epk + ((t < EMBD) ? 0 : 4 * EMBD) + d;
        float acc = 0.f;
#pragma unroll
        for (int l = 0; l < 4; l++) {
            float v = p[l * EMBD];
            acc += v * v;
        }
        if (t < EMBD) s_dA[d] = acc; else s_dB[d] = acc;
        (void)half;
    }
    __syncthreads();

    // Phase 2: one warp per batch row.
    const int warp = tid >> 5;
    const int lane = tid & 31;
    const int b = blockIdx.x * SIM_ROWS + warp;
    const int row = POOL - task_end + k;

    const float4* xq4 = (const float4*)(x_querry + ((size_t)b * POOL + row) * EMBD);
    const float4* ea4 = (const float4*)(e_a + (size_t)k * EMBD);  // L2-hot
    const float4* dA4 = (const float4*)s_dA;
    const float4* dB4 = (const float4*)s_dB;

    float s1 = 0.f, s2 = 0.f, s3 = 0.f;
#pragma unroll
    for (int j = 0; j < ED4 / 32; j++) {   // 6 iterations
        int idx = lane + j * 32;
        float4 x  = xq4[idx];
        float4 e  = __ldg(ea4 + idx);
        float4 ga = dA4[idx];
        float4 gb = dB4[idx];
        float g, a, aa;
        g = ga.x + gb.x; a = x.x * e.x; aa = a * a; s3 += aa; s1 += aa * g; s2 += aa * g * g;
        g = ga.y + gb.y; a = x.y * e.y; aa = a * a; s3 += aa; s1 += aa * g; s2 += aa * g * g;
        g = ga.z + gb.z; a = x.z * e.z; aa = a * a; s3 += aa; s1 += aa * g; s2 += aa * g * g;
        g = ga.w + gb.w; a = x.w * e.w; aa = a * a; s3 += aa; s1 += aa * g; s2 += aa * g * g;
    }
#pragma unroll
    for (int o = 16; o > 0; o >>= 1) {
        s1 += __shfl_down_sync(0xFFFFFFFFu, s1, o);
        s2 += __shfl_down_sync(0xFFFFFFFFu, s2, o);
        s3 += __shfl_down_sync(0xFFFFFFFFu, s3, o);
    }
    if (lane == 0) {
        const float eps = 1e-12f;
        float n1 = fmaxf(sqrtf(s2), eps);
        float n2 = fmaxf(sqrtf(s3), eps);
        g_sim[(size_t)b * POOL + k] = s1 / (n1 * n2);
    }
}

// ---------------------------------------------------------------------------
// Kernel B: mega — round-15 proven config (96.2 us, regs 40), byte-identical:
//   blocks [0,512): pmt einsum (1 batch row each); [512,3072): copy.
// ---------------------------------------------------------------------------
__global__ void __launch_bounds__(256) mega_kernel(
        const float* __restrict__ e_p,
        const float* __restrict__ x_block,
        const int*   __restrict__ task_id_p,
        float* __restrict__ out,
        size_t xb_float4s) {
    if (blockIdx.x < PMT_BLOCKS) {
        // ---- einsum: int_pmt[b,l,d] = sum_k sim[b,k] * e_p[k,l,d] ----
        const int task_end = (*task_id_p + 1) * NB_PT;
        const int b = blockIdx.x;

        __shared__ float s_sim[POOL];
        if (threadIdx.x < POOL)
            s_sim[threadIdx.x] = g_sim[(size_t)b * POOL + threadIdx.x];
        __syncthreads();

        const float4* ep4 = (const float4*)e_p;
        const size_t KEY4 = (size_t)BATCH * (PLEN / 2) * ED4;

        for (int idx = threadIdx.x; idx < PLEN * ED4; idx += 256) {
            int l  = idx / ED4;
            int d4 = idx % ED4;
            float4 acc = make_float4(0.f, 0.f, 0.f, 0.f);
            for (int kk = 0; kk < task_end; kk++) {
                float s  = s_sim[kk];
                float4 v = ep4[((size_t)kk * PLEN + l) * ED4 + d4];
                acc.x += s * v.x; acc.y += s * v.y;
                acc.z += s * v.z; acc.w += s * v.w;
            }
            float4* o4;
            if (l < PLEN / 2)
                o4 = (float4*)out + ((size_t)b * (PLEN / 2) + l) * ED4 + d4;
            else
                o4 = (float4*)out + KEY4 +
                     ((size_t)b * (PLEN / 2) + (l - PLEN / 2)) * ED4 + d4;
            *o4 = acc;
        }
    } else {
        // ---- streaming copy: x_block -> out tail ----
        const float4* src = (const float4*)x_block;
        float4* dst = (float4*)(out + (size_t)BATCH * PLEN * EMBD);

        const size_t stride = (size_t)COPY_BLOCKS * 256;
        size_t i = (size_t)(blockIdx.x - PMT_BLOCKS) * 256 + threadIdx.x;

        for (; i + 3 * stride < xb_float4s; i += 4 * stride) {
            float4 v0 = __ldcs(src + i);
            float4 v1 = __ldcs(src + i + stride);
            float4 v2 = __ldcs(src + i + 2 * stride);
            float4 v3 = __ldcs(src + i + 3 * stride);
            __stcs(dst + i,              v0);
            __stcs(dst + i + stride,     v1);
            __stcs(dst + i + 2 * stride, v2);
            __stcs(dst + i + 3 * stride, v3);
        }
        for (; i < xb_float4s; i += stride)
            __stcs(dst + i, __ldcs(src + i));
    }
}

// ---------------------------------------------------------------------------
// Launch — two kernels: sim_fused -> mega(pmt+copy).
// Inputs (metadata order): x_querry, x_block, e_a, e_p, idx, task_id
// ---------------------------------------------------------------------------
extern "C" void kernel_launch(void* const* d_in, const int* in_sizes, int n_in,
                              void* d_out, int out_size) {
    const float* x_querry = (const float*)d_in[0];
    const float* x_block  = (const float*)d_in[1];
    const float* e_a      = (const float*)d_in[2];
    const float* e_p      = (const float*)d_in[3];
    const int*   task_id  = (const int*)d_in[5];
    float* out = (float*)d_out;

    dim3 sim_grid(SIM_G, POOL);
    sim_fused_kernel<<<sim_grid, SIM_THREADS>>>(x_querry, e_a, e_p, task_id);

    size_t xb_float4s = (size_t)in_sizes[1] / 4;
    mega_kernel<<<PMT_BLOCKS + COPY_BLOCKS, 256>>>(
        e_p, x_block, task_id, out, xb_float4s);
}